// round 10
// baseline (speedup 1.0000x reference)
#include <cuda_runtime.h>
#include <cuda_fp16.h>
#include <math.h>
#include <stdint.h>

// Problem constants: B=64, T=2048, D=U=128
#define PB 64
#define PT 2048
#define PD 128
#define PU 128
#define NROWS (PB * PT)           // 131072
#define NWTILES (NROWS / 16)      // 8192 warp-tiles of 16 rows
#define SGRID 296                 // 2 CTAs/SM
#define K1_WARPS 8
#define K1_THREADS (K1_WARPS * 32)
#define TOTAL_WARPS (SGRID * K1_WARPS)   // 2368
#define CH2 8                     // context chunks per batch
#define TC2 256                   // t's per chunk

// W smem: 128 rows x (256B data + 16B pad)
#define WPITCH 272
#define WBYTES (PD * WPITCH)      // 34816 (static smem)

// ---------------- device scratch ----------------
__device__ float g_score[NROWS];
__device__ float g_max[PB];
__device__ float g_rcp[PB];
__device__ __align__(16) float g_partial[PB * CH2 * PD];
__device__ unsigned int g_cnt[PB];     // zero-init; self-resetting per launch

// ---------------- helpers ----------------
__device__ __forceinline__ uint32_t smem_u32(const void* p) {
    uint32_t a;
    asm("{ .reg .u64 t; cvta.to.shared.u64 t, %1; cvt.u32.u64 %0, t; }" : "=r"(a) : "l"(p));
    return a;
}
__device__ __forceinline__ uint32_t pack_h2(float a, float b) {
    __half2 h = __floats2half2_rn(a, b);
    return *reinterpret_cast<uint32_t*>(&h);
}
__device__ __forceinline__ float hw_tanh(float x) {
    float y;
    asm("tanh.approx.f32 %0, %1;" : "=f"(y) : "f"(x));
    return y;
}
#define LDSM4T(r0, r1, r2, r3, addr) \
    asm volatile("ldmatrix.sync.aligned.m8n8.x4.trans.shared.b16 {%0,%1,%2,%3}, [%4];" \
                 : "=r"(r0), "=r"(r1), "=r"(r2), "=r"(r3) : "r"(addr))
#define MMA16816H(d0, d1, d2, d3, a0, a1, a2, a3, b0, b1) \
    asm volatile("mma.sync.aligned.m16n8k16.row.col.f32.f16.f16.f32 " \
                 "{%0,%1,%2,%3}, {%4,%5,%6,%7}, {%8,%9}, {%0,%1,%2,%3};" \
                 : "+f"(d0), "+f"(d1), "+f"(d2), "+f"(d3) \
                 : "r"(a0), "r"(a1), "r"(a2), "r"(a3), "r"(b0), "r"(b1))

// ================= K1: mma.sync score kernel (fp16 1-pass) =================
__global__ void __launch_bounds__(K1_THREADS, 2)
score_kernel(const float* __restrict__ enc,
             const float* __restrict__ W1w, const float* __restrict__ W1b,
             const float* __restrict__ W2w, const float* __restrict__ W2b,
             const float* __restrict__ Vw) {
    __shared__ __align__(16) char Wsm[WBYTES];
    __shared__ float bias_s[PU], V_s[PU];

    const int tid = threadIdx.x, warp = tid >> 5, lane = tid & 31;
    const int g = lane >> 2, c = lane & 3;

    // fold W1+W2 -> fp16 into padded smem (row=d, col=u); L2-hot after CTA 0
    for (int i = tid; i < PD * PU; i += K1_THREADS) {
        int d = i >> 7, u = i & 127;
        *(__half*)(Wsm + d * WPITCH + u * 2) = __float2half_rn(W1w[i] + W2w[i]);
    }
    if (tid < PU) {
        bias_s[tid] = W1b[tid] + W2b[tid];
        V_s[tid] = Vw[tid];               // V_b softmax-invariant, dropped
    }
    __syncthreads();

    // ldmatrix lane offset (verified mapping)
    const uint32_t lr = lane & 7, lg = lane >> 3;
    const uint32_t lds_off = (lr + ((lg & 1) << 3)) * WPITCH + ((lg >> 1) << 3) * 2;
    const uint32_t wh_a = smem_u32(Wsm) + lds_off;

    const int gw = blockIdx.x * K1_WARPS + warp;

    for (int wt = gw; wt < NWTILES; wt += TOTAL_WARPS) {
        const long row0 = (long)wt * 16;
        const float* xr  = enc + (row0 + g) * PD + 2 * c;
        const float* xr8 = xr + 8 * PD;

        // batch ALL A loads up front (32 independent LDG.64 -> MLP ~32)
        uint32_t Ah[8][4];
        #pragma unroll
        for (int k = 0; k < 8; k++) {
            float2 p00 = *(const float2*)(xr  + k * 16);
            float2 p10 = *(const float2*)(xr8 + k * 16);
            float2 p01 = *(const float2*)(xr  + k * 16 + 8);
            float2 p11 = *(const float2*)(xr8 + k * 16 + 8);
            Ah[k][0] = pack_h2(p00.x, p00.y);
            Ah[k][1] = pack_h2(p10.x, p10.y);
            Ah[k][2] = pack_h2(p01.x, p01.y);
            Ah[k][3] = pack_h2(p11.x, p11.y);
        }

        float acc[16][4];
        #pragma unroll
        for (int np = 0; np < 16; np++) {
            float2 bb = *(const float2*)&bias_s[np * 8 + 2 * c];
            acc[np][0] = bb.x; acc[np][1] = bb.y;
            acc[np][2] = bb.x; acc[np][3] = bb.y;
        }

        #pragma unroll
        for (int k = 0; k < 8; k++) {
            const uint32_t koff = (uint32_t)k * (16 * WPITCH);
            #pragma unroll
            for (int np2 = 0; np2 < 8; np2++) {
                uint32_t b0, b1, b2, b3;
                LDSM4T(b0, b1, b2, b3, wh_a + koff + np2 * 32);
                float* a0 = acc[np2 * 2];
                float* a1 = acc[np2 * 2 + 1];
                MMA16816H(a0[0], a0[1], a0[2], a0[3], Ah[k][0], Ah[k][1], Ah[k][2], Ah[k][3], b0, b1);
                MMA16816H(a1[0], a1[1], a1[2], a1[3], Ah[k][0], Ah[k][1], Ah[k][2], Ah[k][3], b2, b3);
            }
        }

        // epilogue: HW tanh + V-dot, quad reduce
        float pg = 0.0f, pg8 = 0.0f;
        #pragma unroll
        for (int np = 0; np < 16; np++) {
            float2 vv = *(const float2*)&V_s[np * 8 + 2 * c];
            pg  = fmaf(vv.x, hw_tanh(acc[np][0]), pg);
            pg  = fmaf(vv.y, hw_tanh(acc[np][1]), pg);
            pg8 = fmaf(vv.x, hw_tanh(acc[np][2]), pg8);
            pg8 = fmaf(vv.y, hw_tanh(acc[np][3]), pg8);
        }
        pg  += __shfl_xor_sync(0xFFFFFFFFu, pg, 1);
        pg  += __shfl_xor_sync(0xFFFFFFFFu, pg, 2);
        pg8 += __shfl_xor_sync(0xFFFFFFFFu, pg8, 1);
        pg8 += __shfl_xor_sync(0xFFFFFFFFu, pg8, 2);
        if (c == 0) {
            g_score[row0 + g] = pg;
            g_score[row0 + g + 8] = pg8;
        }
    }
}

// ================= K2: per-batch softmax stats =================
__global__ void softmax_stats_kernel() {
    const int b = blockIdx.x;
    const int tid = threadIdx.x;  // 256
    __shared__ float red[256];
    const float* s = g_score + b * PT;

    float m = -1e30f;
    for (int t = tid; t < PT; t += 256) m = fmaxf(m, s[t]);
    red[tid] = m;
    __syncthreads();
    for (int o = 128; o > 0; o >>= 1) {
        if (tid < o) red[tid] = fmaxf(red[tid], red[tid + o]);
        __syncthreads();
    }
    m = red[0];
    __syncthreads();

    float sum = 0.0f;
    for (int t = tid; t < PT; t += 256) sum += expf(s[t] - m);
    red[tid] = sum;
    __syncthreads();
    for (int o = 128; o > 0; o >>= 1) {
        if (tid < o) red[tid] += red[tid + o];
        __syncthreads();
    }
    if (tid == 0) { g_max[b] = m; g_rcp[b] = 1.0f / red[0]; }
}

// ================= K3: partial contexts + fused final reduce =================
// grid (CH2, PB), 256 threads. Each block: 256 t's. Last block per batch
// (threadfence + atomic counter, CUDA threadFenceReduction pattern) sums the
// CH2 partials in fixed chunk order -> deterministic.
__global__ void __launch_bounds__(256)
context_kernel(const float* __restrict__ enc, float* __restrict__ out) {
    const int cb = blockIdx.x, b = blockIdx.y;
    const int tid = threadIdx.x;              // 256
    const int d4 = tid & 31, tg = tid >> 5;   // 32 d-lanes x 8 t-groups
    __shared__ float wgt[TC2];
    __shared__ float4 part[256];
    __shared__ bool isLast;

    const float m = g_max[b], rcp = g_rcp[b];
    wgt[tid] = expf(g_score[b * PT + cb * TC2 + tid] - m) * rcp;
    __syncthreads();

    const float4* x = (const float4*)(enc + ((long)b * PT + cb * TC2) * PD);
    float4 a = make_float4(0.f, 0.f, 0.f, 0.f);
    #pragma unroll
    for (int t = tg; t < TC2; t += 8) {
        const float w = wgt[t];
        const float4 v = x[t * 32 + d4];
        a.x = fmaf(w, v.x, a.x); a.y = fmaf(w, v.y, a.y);
        a.z = fmaf(w, v.z, a.z); a.w = fmaf(w, v.w, a.w);
    }
    part[tid] = a;
    __syncthreads();
    if (tg == 0) {
        float4 r = make_float4(0.f, 0.f, 0.f, 0.f);
        #pragma unroll
        for (int j = 0; j < 8; j++) {
            float4 p = part[j * 32 + d4];
            r.x += p.x; r.y += p.y; r.z += p.z; r.w += p.w;
        }
        ((float4*)(g_partial + (b * CH2 + cb) * PD))[d4] = r;
    }

    // last-block-done final reduce for this batch
    __threadfence();
    __syncthreads();
    if (tid == 0) {
        unsigned int v = atomicAdd(&g_cnt[b], 1u);
        isLast = (v == CH2 - 1);
    }
    __syncthreads();
    if (isLast) {
        if (tid < PD) {
            float accf = 0.0f;
            #pragma unroll
            for (int cc = 0; cc < CH2; cc++)
                accf += g_partial[(b * CH2 + cc) * PD + tid];
            out[b * PD + tid] = accf;
        }
        if (tid == 0) g_cnt[b] = 0;     // reset for next graph replay
    }
}

// ================= launch =================
extern "C" void kernel_launch(void* const* d_in, const int* in_sizes, int n_in,
                              void* d_out, int out_size) {
    const float* enc = (const float*)d_in[0];
    const float* W1w = (const float*)d_in[1];
    const float* W1b = (const float*)d_in[2];
    const float* W2w = (const float*)d_in[3];
    const float* W2b = (const float*)d_in[4];
    const float* Vw  = (const float*)d_in[5];
    float* out = (float*)d_out;

    score_kernel<<<SGRID, K1_THREADS>>>(enc, W1w, W1b, W2w, W2b, Vw);
    softmax_stats_kernel<<<PB, 256>>>();
    dim3 g3(CH2, PB);
    context_kernel<<<g3, 256>>>(enc, out);
}

// round 11
// speedup vs baseline: 1.0317x; 1.0317x over previous
#include <cuda_runtime.h>
#include <cuda_fp16.h>
#include <math.h>
#include <stdint.h>

// Problem constants: B=64, T=2048, D=U=128
#define PB 64
#define PT 2048
#define PD 128
#define PU 128
#define NROWS (PB * PT)           // 131072
#define NWTILES (NROWS / 16)      // 8192 warp-tiles of 16 rows
#define SGRID 148                 // 1 CTA/SM (round-8 best config)
#define K1_WARPS 12
#define K1_THREADS (K1_WARPS * 32)
#define TOTAL_WARPS (SGRID * K1_WARPS)   // 1776
#define CH2 8                     // context chunks per batch
#define TC2 256                   // t's per chunk

// W smem: 128 rows x (256B data + 16B pad)
#define WPITCH 272
#define WBYTES (PD * WPITCH)      // 34816 (static smem)

// ---------------- device scratch ----------------
__device__ float g_score[NROWS];
__device__ __align__(16) float g_partial[PB * CH2 * PD];
__device__ unsigned int g_cnt[PB];     // zero-init; self-resetting per launch

// ---------------- helpers ----------------
__device__ __forceinline__ uint32_t smem_u32(const void* p) {
    uint32_t a;
    asm("{ .reg .u64 t; cvta.to.shared.u64 t, %1; cvt.u32.u64 %0, t; }" : "=r"(a) : "l"(p));
    return a;
}
__device__ __forceinline__ uint32_t pack_h2(float a, float b) {
    __half2 h = __floats2half2_rn(a, b);
    return *reinterpret_cast<uint32_t*>(&h);
}
__device__ __forceinline__ float hw_tanh(float x) {
    float y;
    asm("tanh.approx.f32 %0, %1;" : "=f"(y) : "f"(x));
    return y;
}
#define LDSM4T(r0, r1, r2, r3, addr) \
    asm volatile("ldmatrix.sync.aligned.m8n8.x4.trans.shared.b16 {%0,%1,%2,%3}, [%4];" \
                 : "=r"(r0), "=r"(r1), "=r"(r2), "=r"(r3) : "r"(addr))
#define MMA16816H(d0, d1, d2, d3, a0, a1, a2, a3, b0, b1) \
    asm volatile("mma.sync.aligned.m16n8k16.row.col.f32.f16.f16.f32 " \
                 "{%0,%1,%2,%3}, {%4,%5,%6,%7}, {%8,%9}, {%0,%1,%2,%3};" \
                 : "+f"(d0), "+f"(d1), "+f"(d2), "+f"(d3) \
                 : "r"(a0), "r"(a1), "r"(a2), "r"(a3), "r"(b0), "r"(b1))

// ================= K1: mma.sync score kernel (fp16 1-pass, round-8 config) ==
__global__ void __launch_bounds__(K1_THREADS, 1)
score_kernel(const float* __restrict__ enc,
             const float* __restrict__ W1w, const float* __restrict__ W1b,
             const float* __restrict__ W2w, const float* __restrict__ W2b,
             const float* __restrict__ Vw) {
    __shared__ __align__(16) char Wsm[WBYTES];
    __shared__ float bias_s[PU], V_s[PU];

    const int tid = threadIdx.x, warp = tid >> 5, lane = tid & 31;
    const int g = lane >> 2, c = lane & 3;

    // fold W1+W2 -> fp16 into padded smem (row=d, col=u); L2-hot after CTA 0
    for (int i = tid; i < PD * PU; i += K1_THREADS) {
        int d = i >> 7, u = i & 127;
        *(__half*)(Wsm + d * WPITCH + u * 2) = __float2half_rn(W1w[i] + W2w[i]);
    }
    if (tid < PU) {
        bias_s[tid] = W1b[tid] + W2b[tid];
        V_s[tid] = Vw[tid];               // V_b softmax-invariant, dropped
    }
    __syncthreads();

    // ldmatrix lane offset (verified mapping)
    const uint32_t lr = lane & 7, lg = lane >> 3;
    const uint32_t lds_off = (lr + ((lg & 1) << 3)) * WPITCH + ((lg >> 1) << 3) * 2;
    const uint32_t wh_a = smem_u32(Wsm) + lds_off;

    const int gw = blockIdx.x * K1_WARPS + warp;

    for (int wt = gw; wt < NWTILES; wt += TOTAL_WARPS) {
        const long row0 = (long)wt * 16;
        const float* xr  = enc + (row0 + g) * PD + 2 * c;
        const float* xr8 = xr + 8 * PD;

        float acc[16][4];
        #pragma unroll
        for (int np = 0; np < 16; np++) {
            float2 bb = *(const float2*)&bias_s[np * 8 + 2 * c];
            acc[np][0] = bb.x; acc[np][1] = bb.y;
            acc[np][2] = bb.x; acc[np][3] = bb.y;
        }

        #pragma unroll
        for (int k = 0; k < 8; k++) {
            float2 p00 = *(const float2*)(xr  + k * 16);
            float2 p10 = *(const float2*)(xr8 + k * 16);
            float2 p01 = *(const float2*)(xr  + k * 16 + 8);
            float2 p11 = *(const float2*)(xr8 + k * 16 + 8);
            uint32_t Ah[4];
            Ah[0] = pack_h2(p00.x, p00.y);
            Ah[1] = pack_h2(p10.x, p10.y);
            Ah[2] = pack_h2(p01.x, p01.y);
            Ah[3] = pack_h2(p11.x, p11.y);

            const uint32_t koff = (uint32_t)k * (16 * WPITCH);
            #pragma unroll
            for (int np2 = 0; np2 < 8; np2++) {
                uint32_t b0, b1, b2, b3;
                LDSM4T(b0, b1, b2, b3, wh_a + koff + np2 * 32);
                float* a0 = acc[np2 * 2];
                float* a1 = acc[np2 * 2 + 1];
                MMA16816H(a0[0], a0[1], a0[2], a0[3], Ah[0], Ah[1], Ah[2], Ah[3], b0, b1);
                MMA16816H(a1[0], a1[1], a1[2], a1[3], Ah[0], Ah[1], Ah[2], Ah[3], b2, b3);
            }
        }

        // epilogue: HW tanh + V-dot, quad reduce
        float pg = 0.0f, pg8 = 0.0f;
        #pragma unroll
        for (int np = 0; np < 16; np++) {
            float2 vv = *(const float2*)&V_s[np * 8 + 2 * c];
            pg  = fmaf(vv.x, hw_tanh(acc[np][0]), pg);
            pg  = fmaf(vv.y, hw_tanh(acc[np][1]), pg);
            pg8 = fmaf(vv.x, hw_tanh(acc[np][2]), pg8);
            pg8 = fmaf(vv.y, hw_tanh(acc[np][3]), pg8);
        }
        pg  += __shfl_xor_sync(0xFFFFFFFFu, pg, 1);
        pg  += __shfl_xor_sync(0xFFFFFFFFu, pg, 2);
        pg8 += __shfl_xor_sync(0xFFFFFFFFu, pg8, 1);
        pg8 += __shfl_xor_sync(0xFFFFFFFFu, pg8, 2);
        if (c == 0) {
            g_score[row0 + g] = pg;
            g_score[row0 + g + 8] = pg8;
        }
    }
}

// ================= K2: context kernel (inline softmax stats + fused reduce) ==
// grid (CH2, PB), 256 threads. Every block of batch b computes the SAME
// (max, 1/sumexp) with the SAME deterministic reduction -> identical weights.
// Last block per batch (threadfence + counter) emits the final context row.
__global__ void __launch_bounds__(256)
context_kernel(const float* __restrict__ enc, float* __restrict__ out) {
    const int cb = blockIdx.x, b = blockIdx.y;
    const int tid = threadIdx.x;              // 256
    const int d4 = tid & 31, tg = tid >> 5;   // 32 d-lanes x 8 t-groups
    __shared__ float red[256];
    __shared__ float wgt[TC2];
    __shared__ float4 part[256];
    __shared__ bool isLast;

    // ---- inline softmax stats over the full batch (deterministic) ----
    const float* s = g_score + b * PT;
    float mx = -1e30f;
    for (int t = tid; t < PT; t += 256) mx = fmaxf(mx, s[t]);
    red[tid] = mx;
    __syncthreads();
    for (int o = 128; o > 0; o >>= 1) {
        if (tid < o) red[tid] = fmaxf(red[tid], red[tid + o]);
        __syncthreads();
    }
    const float m = red[0];
    __syncthreads();
    float sum = 0.0f;
    for (int t = tid; t < PT; t += 256) sum += expf(s[t] - m);
    red[tid] = sum;
    __syncthreads();
    for (int o = 128; o > 0; o >>= 1) {
        if (tid < o) red[tid] += red[tid + o];
        __syncthreads();
    }
    const float rcp = 1.0f / red[0];

    // ---- weights for this chunk ----
    wgt[tid] = expf(s[cb * TC2 + tid] - m) * rcp;
    __syncthreads();

    // ---- weighted sum over this chunk's 256 t's ----
    const float4* x = (const float4*)(enc + ((long)b * PT + cb * TC2) * PD);
    float4 a = make_float4(0.f, 0.f, 0.f, 0.f);
    #pragma unroll
    for (int t = tg; t < TC2; t += 8) {
        const float w = wgt[t];
        const float4 v = x[t * 32 + d4];
        a.x = fmaf(w, v.x, a.x); a.y = fmaf(w, v.y, a.y);
        a.z = fmaf(w, v.z, a.z); a.w = fmaf(w, v.w, a.w);
    }
    part[tid] = a;
    __syncthreads();
    if (tg == 0) {
        float4 r = make_float4(0.f, 0.f, 0.f, 0.f);
        #pragma unroll
        for (int j = 0; j < 8; j++) {
            float4 p = part[j * 32 + d4];
            r.x += p.x; r.y += p.y; r.z += p.z; r.w += p.w;
        }
        ((float4*)(g_partial + (b * CH2 + cb) * PD))[d4] = r;
    }

    // ---- last-block-done final reduce for this batch ----
    __threadfence();
    __syncthreads();
    if (tid == 0) {
        unsigned int v = atomicAdd(&g_cnt[b], 1u);
        isLast = (v == CH2 - 1);
    }
    __syncthreads();
    if (isLast) {
        if (tid < PD) {
            float accf = 0.0f;
            #pragma unroll
            for (int cc = 0; cc < CH2; cc++)
                accf += g_partial[(b * CH2 + cc) * PD + tid];
            out[b * PD + tid] = accf;
        }
        if (tid == 0) g_cnt[b] = 0;     // reset for next graph replay
    }
}

// ================= launch =================
extern "C" void kernel_launch(void* const* d_in, const int* in_sizes, int n_in,
                              void* d_out, int out_size) {
    const float* enc = (const float*)d_in[0];
    const float* W1w = (const float*)d_in[1];
    const float* W1b = (const float*)d_in[2];
    const float* W2w = (const float*)d_in[3];
    const float* W2b = (const float*)d_in[4];
    const float* Vw  = (const float*)d_in[5];
    float* out = (float*)d_out;

    score_kernel<<<SGRID, K1_THREADS>>>(enc, W1w, W1b, W2w, W2b, Vw);
    dim3 g3(CH2, PB);
    context_kernel<<<g3, 256>>>(enc, out);
}

// round 14
// speedup vs baseline: 1.0792x; 1.0460x over previous
#include <cuda_runtime.h>
#include <cuda_fp16.h>
#include <math.h>
#include <stdint.h>

// Problem constants: B=64, T=2048, D=U=128
#define PB 64
#define PT 2048
#define PD 128
#define PU 128
#define NROWS (PB * PT)           // 131072
#define NWTILES (NROWS / 16)      // 8192 warp-tiles of 16 rows
#define SGRID 148                 // 1 CTA/SM (best score config)
#define K1_WARPS 12
#define K1_THREADS (K1_WARPS * 32)
#define TOTAL_WARPS (SGRID * K1_WARPS)   // 1776
#define CH 16                     // context chunks per batch
#define TCH 128                   // t's per chunk

// W smem: 128 rows x (256B data + 16B pad)
#define WPITCH 272
#define WBYTES (PD * WPITCH)      // 34816 (static smem)

// ---------------- device scratch ----------------
__device__ float g_escore[NROWS];              // exp(score)
__device__ __align__(16) float g_partial[PB * CH * PD];
__device__ unsigned int g_cnt[PB];             // zero-init; self-resetting

// ---------------- helpers ----------------
__device__ __forceinline__ uint32_t smem_u32(const void* p) {
    uint32_t a;
    asm("{ .reg .u64 t; cvta.to.shared.u64 t, %1; cvt.u32.u64 %0, t; }" : "=r"(a) : "l"(p));
    return a;
}
__device__ __forceinline__ uint32_t pack_h2(float a, float b) {
    __half2 h = __floats2half2_rn(a, b);
    return *reinterpret_cast<uint32_t*>(&h);
}
__device__ __forceinline__ float hw_tanh(float x) {
    float y;
    asm("tanh.approx.f32 %0, %1;" : "=f"(y) : "f"(x));
    return y;
}
#define LDSM4T(r0, r1, r2, r3, addr) \
    asm volatile("ldmatrix.sync.aligned.m8n8.x4.trans.shared.b16 {%0,%1,%2,%3}, [%4];" \
                 : "=r"(r0), "=r"(r1), "=r"(r2), "=r"(r3) : "r"(addr))
#define MMA16816H(d0, d1, d2, d3, a0, a1, a2, a3, b0, b1) \
    asm volatile("mma.sync.aligned.m16n8k16.row.col.f32.f16.f16.f32 " \
                 "{%0,%1,%2,%3}, {%4,%5,%6,%7}, {%8,%9}, {%0,%1,%2,%3};" \
                 : "+f"(d0), "+f"(d1), "+f"(d2), "+f"(d3) \
                 : "r"(a0), "r"(a1), "r"(a2), "r"(a3), "r"(b0), "r"(b1))

// ================= K1: mma.sync score kernel -> writes exp(score) ==========
// Scores are bounded: |s| <= sum|V_u| * max|tanh| ~ 9, so exp(s) <= ~8e3 and
// softmax(s) = e^s / sum e^s needs no max shift (identical result).
__global__ void __launch_bounds__(K1_THREADS, 1)
score_kernel(const float* __restrict__ enc,
             const float* __restrict__ W1w, const float* __restrict__ W1b,
             const float* __restrict__ W2w, const float* __restrict__ W2b,
             const float* __restrict__ Vw) {
    __shared__ __align__(16) char Wsm[WBYTES];
    __shared__ float bias_s[PU], V_s[PU];

    const int tid = threadIdx.x, warp = tid >> 5, lane = tid & 31;
    const int g = lane >> 2, c = lane & 3;

    // fold W1+W2 -> fp16 into padded smem (row=d, col=u); L2-hot after CTA 0
    for (int i = tid; i < PD * PU; i += K1_THREADS) {
        int d = i >> 7, u = i & 127;
        *(__half*)(Wsm + d * WPITCH + u * 2) = __float2half_rn(W1w[i] + W2w[i]);
    }
    if (tid < PU) {
        bias_s[tid] = W1b[tid] + W2b[tid];
        V_s[tid] = Vw[tid];               // V_b softmax-invariant, dropped
    }
    __syncthreads();

    // ldmatrix lane offset (verified mapping)
    const uint32_t lr = lane & 7, lg = lane >> 3;
    const uint32_t lds_off = (lr + ((lg & 1) << 3)) * WPITCH + ((lg >> 1) << 3) * 2;
    const uint32_t wh_a = smem_u32(Wsm) + lds_off;

    const int gw = blockIdx.x * K1_WARPS + warp;

    for (int wt = gw; wt < NWTILES; wt += TOTAL_WARPS) {
        const long row0 = (long)wt * 16;
        const float* xr  = enc + (row0 + g) * PD + 2 * c;
        const float* xr8 = xr + 8 * PD;

        float acc[16][4];
        #pragma unroll
        for (int np = 0; np < 16; np++) {
            float2 bb = *(const float2*)&bias_s[np * 8 + 2 * c];
            acc[np][0] = bb.x; acc[np][1] = bb.y;
            acc[np][2] = bb.x; acc[np][3] = bb.y;
        }

        #pragma unroll
        for (int k = 0; k < 8; k++) {
            float2 p00 = *(const float2*)(xr  + k * 16);
            float2 p10 = *(const float2*)(xr8 + k * 16);
            float2 p01 = *(const float2*)(xr  + k * 16 + 8);
            float2 p11 = *(const float2*)(xr8 + k * 16 + 8);
            uint32_t Ah[4];
            Ah[0] = pack_h2(p00.x, p00.y);
            Ah[1] = pack_h2(p10.x, p10.y);
            Ah[2] = pack_h2(p01.x, p01.y);
            Ah[3] = pack_h2(p11.x, p11.y);

            const uint32_t koff = (uint32_t)k * (16 * WPITCH);
            #pragma unroll
            for (int np2 = 0; np2 < 8; np2++) {
                uint32_t b0, b1, b2, b3;
                LDSM4T(b0, b1, b2, b3, wh_a + koff + np2 * 32);
                float* a0 = acc[np2 * 2];
                float* a1 = acc[np2 * 2 + 1];
                MMA16816H(a0[0], a0[1], a0[2], a0[3], Ah[0], Ah[1], Ah[2], Ah[3], b0, b1);
                MMA16816H(a1[0], a1[1], a1[2], a1[3], Ah[0], Ah[1], Ah[2], Ah[3], b2, b3);
            }
        }

        // epilogue: HW tanh + V-dot, quad reduce, write exp(score)
        float pg = 0.0f, pg8 = 0.0f;
        #pragma unroll
        for (int np = 0; np < 16; np++) {
            float2 vv = *(const float2*)&V_s[np * 8 + 2 * c];
            pg  = fmaf(vv.x, hw_tanh(acc[np][0]), pg);
            pg  = fmaf(vv.y, hw_tanh(acc[np][1]), pg);
            pg8 = fmaf(vv.x, hw_tanh(acc[np][2]), pg8);
            pg8 = fmaf(vv.y, hw_tanh(acc[np][3]), pg8);
        }
        pg  += __shfl_xor_sync(0xFFFFFFFFu, pg, 1);
        pg  += __shfl_xor_sync(0xFFFFFFFFu, pg, 2);
        pg8 += __shfl_xor_sync(0xFFFFFFFFu, pg8, 1);
        pg8 += __shfl_xor_sync(0xFFFFFFFFu, pg8, 2);
        if (c == 0) {
            g_escore[row0 + g] = expf(pg);
            g_escore[row0 + g + 8] = expf(pg8);
        }
    }
}

// ================= K2: context kernel (sum-only stats + fused reduce) =======
// grid (CH, PB), 256 threads. Stats = single sum over 2048 precomputed e's
// (L2-hot) with shuffle reduce -> identical deterministic value in all blocks.
__global__ void __launch_bounds__(256)
context_kernel(const float* __restrict__ enc, float* __restrict__ out) {
    const int cb = blockIdx.x, b = blockIdx.y;
    const int tid = threadIdx.x;              // 256
    const int lane = tid & 31, wid = tid >> 5;
    const int d4 = tid & 31, tg = tid >> 5;   // 32 d-lanes x 8 t-groups
    __shared__ float red[8];
    __shared__ float wgt[TCH];
    __shared__ float4 part[256];
    __shared__ bool isLast;

    // ---- sum of e over the batch (deterministic, cheap) ----
    const float* e = g_escore + b * PT;
    float sum = 0.0f;
    #pragma unroll
    for (int t = tid; t < PT; t += 256) sum += e[t];
    #pragma unroll
    for (int o = 16; o > 0; o >>= 1) sum += __shfl_xor_sync(0xFFFFFFFFu, sum, o);
    if (lane == 0) red[wid] = sum;
    __syncthreads();
    const float rcp = 1.0f / (((red[0] + red[1]) + (red[2] + red[3]))
                            + ((red[4] + red[5]) + (red[6] + red[7])));

    // ---- weights for this 128-t chunk ----
    if (tid < TCH) wgt[tid] = e[cb * TCH + tid] * rcp;
    __syncthreads();

    // ---- weighted sum over this chunk ----
    const float4* x = (const float4*)(enc + ((long)b * PT + cb * TCH) * PD);
    float4 a = make_float4(0.f, 0.f, 0.f, 0.f);
    #pragma unroll
    for (int t = tg; t < TCH; t += 8) {
        const float w = wgt[t];
        const float4 v = x[t * 32 + d4];
        a.x = fmaf(w, v.x, a.x); a.y = fmaf(w, v.y, a.y);
        a.z = fmaf(w, v.z, a.z); a.w = fmaf(w, v.w, a.w);
    }
    part[tid] = a;
    __syncthreads();
    if (tg == 0) {
        float4 r = make_float4(0.f, 0.f, 0.f, 0.f);
        #pragma unroll
        for (int j = 0; j < 8; j++) {
            float4 p = part[j * 32 + d4];
            r.x += p.x; r.y += p.y; r.z += p.z; r.w += p.w;
        }
        ((float4*)(g_partial + (b * CH + cb) * PD))[d4] = r;
    }

    // ---- last-block-done final reduce for this batch ----
    __threadfence();
    __syncthreads();
    if (tid == 0) {
        unsigned int v = atomicAdd(&g_cnt[b], 1u);
        isLast = (v == CH - 1);
    }
    __syncthreads();
    if (isLast) {
        if (tid < PD) {
            float accf = 0.0f;
            #pragma unroll
            for (int cc = 0; cc < CH; cc++)
                accf += g_partial[(b * CH + cc) * PD + tid];
            out[b * PD + tid] = accf;
        }
        if (tid == 0) g_cnt[b] = 0;     // reset for next graph replay
    }
}

// ================= launch =================
extern "C" void kernel_launch(void* const* d_in, const int* in_sizes, int n_in,
                              void* d_out, int out_size) {
    const float* enc = (const float*)d_in[0];
    const float* W1w = (const float*)d_in[1];
    const float* W1b = (const float*)d_in[2];
    const float* W2w = (const float*)d_in[3];
    const float* W2b = (const float*)d_in[4];
    const float* Vw  = (const float*)d_in[5];
    float* out = (float*)d_out;

    score_kernel<<<SGRID, K1_THREADS>>>(enc, W1w, W1b, W2w, W2b, Vw);
    dim3 g3(CH, PB);
    context_kernel<<<g3, 256>>>(enc, out);
}

// round 15
// speedup vs baseline: 1.1429x; 1.0590x over previous
#include <cuda_runtime.h>
#include <cuda_fp16.h>
#include <math.h>
#include <stdint.h>

// Problem constants: B=64, T=2048, D=U=128
#define PB 64
#define PT 2048
#define PD 128
#define PU 128
#define NROWS (PB * PT)           // 131072
#define NWTILES (NROWS / 16)      // 8192 warp-tiles of 16 rows
#define SGRID 148                 // 1 CTA/SM (best score config)
#define K1_WARPS 12
#define K1_THREADS (K1_WARPS * 32)
#define TOTAL_WARPS (SGRID * K1_WARPS)   // 1776
#define CH 16                     // context chunks per batch
#define TCH 128                   // t's per chunk

// W smem: 128 rows x (256B data + 16B pad)
#define WPITCH 272
#define WBYTES (PD * WPITCH)      // 34816 (static smem)

// ---------------- device scratch ----------------
__device__ float g_escore[NROWS];              // exp(score)
__device__ __align__(16) float g_partial[PB * CH * PD];
__device__ unsigned int g_cnt[PB];             // zero-init; self-resetting

// ---------------- helpers ----------------
__device__ __forceinline__ uint32_t smem_u32(const void* p) {
    uint32_t a;
    asm("{ .reg .u64 t; cvta.to.shared.u64 t, %1; cvt.u32.u64 %0, t; }" : "=r"(a) : "l"(p));
    return a;
}
__device__ __forceinline__ uint32_t pack_h2(float a, float b) {
    __half2 h = __floats2half2_rn(a, b);
    return *reinterpret_cast<uint32_t*>(&h);
}
__device__ __forceinline__ float hw_tanh(float x) {
    float y;
    asm("tanh.approx.f32 %0, %1;" : "=f"(y) : "f"(x));
    return y;
}
#define LDSM4T(r0, r1, r2, r3, addr) \
    asm volatile("ldmatrix.sync.aligned.m8n8.x4.trans.shared.b16 {%0,%1,%2,%3}, [%4];" \
                 : "=r"(r0), "=r"(r1), "=r"(r2), "=r"(r3) : "r"(addr))
#define MMA16816H(d0, d1, d2, d3, a0, a1, a2, a3, b0, b1) \
    asm volatile("mma.sync.aligned.m16n8k16.row.col.f32.f16.f16.f32 " \
                 "{%0,%1,%2,%3}, {%4,%5,%6,%7}, {%8,%9}, {%0,%1,%2,%3};" \
                 : "+f"(d0), "+f"(d1), "+f"(d2), "+f"(d3) \
                 : "r"(a0), "r"(a1), "r"(a2), "r"(a3), "r"(b0), "r"(b1))

// ================= K1: mma.sync score kernel -> writes exp(score) ==========
// Scores are bounded: |s| <= sum|V_u| * max|tanh| ~ 9, so exp(s) <= ~8e3 and
// softmax(s) = e^s / sum e^s needs no max shift (identical result).
__global__ void __launch_bounds__(K1_THREADS, 1)
score_kernel(const float* __restrict__ enc,
             const float* __restrict__ W1w, const float* __restrict__ W1b,
             const float* __restrict__ W2w, const float* __restrict__ W2b,
             const float* __restrict__ Vw) {
    __shared__ __align__(16) char Wsm[WBYTES];
    __shared__ float bias_s[PU], V_s[PU];

    const int tid = threadIdx.x, warp = tid >> 5, lane = tid & 31;
    const int g = lane >> 2, c = lane & 3;

    // fold W1+W2 -> fp16 into padded smem (row=d, col=u); L2-hot after CTA 0
    for (int i = tid; i < PD * PU; i += K1_THREADS) {
        int d = i >> 7, u = i & 127;
        *(__half*)(Wsm + d * WPITCH + u * 2) = __float2half_rn(W1w[i] + W2w[i]);
    }
    if (tid < PU) {
        bias_s[tid] = W1b[tid] + W2b[tid];
        V_s[tid] = Vw[tid];               // V_b softmax-invariant, dropped
    }
    __syncthreads();

    // ldmatrix lane offset (verified mapping)
    const uint32_t lr = lane & 7, lg = lane >> 3;
    const uint32_t lds_off = (lr + ((lg & 1) << 3)) * WPITCH + ((lg >> 1) << 3) * 2;
    const uint32_t wh_a = smem_u32(Wsm) + lds_off;

    const int gw = blockIdx.x * K1_WARPS + warp;

    for (int wt = gw; wt < NWTILES; wt += TOTAL_WARPS) {
        const long row0 = (long)wt * 16;
        const float* xr  = enc + (row0 + g) * PD + 2 * c;
        const float* xr8 = xr + 8 * PD;

        float acc[16][4];
        #pragma unroll
        for (int np = 0; np < 16; np++) {
            float2 bb = *(const float2*)&bias_s[np * 8 + 2 * c];
            acc[np][0] = bb.x; acc[np][1] = bb.y;
            acc[np][2] = bb.x; acc[np][3] = bb.y;
        }

        #pragma unroll
        for (int k = 0; k < 8; k++) {
            float2 p00 = *(const float2*)(xr  + k * 16);
            float2 p10 = *(const float2*)(xr8 + k * 16);
            float2 p01 = *(const float2*)(xr  + k * 16 + 8);
            float2 p11 = *(const float2*)(xr8 + k * 16 + 8);
            uint32_t Ah[4];
            Ah[0] = pack_h2(p00.x, p00.y);
            Ah[1] = pack_h2(p10.x, p10.y);
            Ah[2] = pack_h2(p01.x, p01.y);
            Ah[3] = pack_h2(p11.x, p11.y);

            const uint32_t koff = (uint32_t)k * (16 * WPITCH);
            #pragma unroll
            for (int np2 = 0; np2 < 8; np2++) {
                uint32_t b0, b1, b2, b3;
                LDSM4T(b0, b1, b2, b3, wh_a + koff + np2 * 32);
                float* a0 = acc[np2 * 2];
                float* a1 = acc[np2 * 2 + 1];
                MMA16816H(a0[0], a0[1], a0[2], a0[3], Ah[0], Ah[1], Ah[2], Ah[3], b0, b1);
                MMA16816H(a1[0], a1[1], a1[2], a1[3], Ah[0], Ah[1], Ah[2], Ah[3], b2, b3);
            }
        }

        // epilogue: HW tanh + V-dot, quad reduce, write exp(score)
        float pg = 0.0f, pg8 = 0.0f;
        #pragma unroll
        for (int np = 0; np < 16; np++) {
            float2 vv = *(const float2*)&V_s[np * 8 + 2 * c];
            pg  = fmaf(vv.x, hw_tanh(acc[np][0]), pg);
            pg  = fmaf(vv.y, hw_tanh(acc[np][1]), pg);
            pg8 = fmaf(vv.x, hw_tanh(acc[np][2]), pg8);
            pg8 = fmaf(vv.y, hw_tanh(acc[np][3]), pg8);
        }
        pg  += __shfl_xor_sync(0xFFFFFFFFu, pg, 1);
        pg  += __shfl_xor_sync(0xFFFFFFFFu, pg, 2);
        pg8 += __shfl_xor_sync(0xFFFFFFFFu, pg8, 1);
        pg8 += __shfl_xor_sync(0xFFFFFFFFu, pg8, 2);
        if (c == 0) {
            g_escore[row0 + g] = expf(pg);
            g_escore[row0 + g + 8] = expf(pg8);
        }
    }
}

// ================= K2: context kernel (sum-only stats + fused reduce) =======
// grid (CH, PB), 256 threads. Stats = single sum over 2048 precomputed e's
// (L2-hot) with shuffle reduce -> identical deterministic value in all blocks.
__global__ void __launch_bounds__(256)
context_kernel(const float* __restrict__ enc, float* __restrict__ out) {
    const int cb = blockIdx.x, b = blockIdx.y;
    const int tid = threadIdx.x;              // 256
    const int lane = tid & 31, wid = tid >> 5;
    const int d4 = tid & 31, tg = tid >> 5;   // 32 d-lanes x 8 t-groups
    __shared__ float red[8];
    __shared__ float wgt[TCH];
    __shared__ float4 part[256];
    __shared__ bool isLast;

    // ---- sum of e over the batch (deterministic, cheap) ----
    const float* e = g_escore + b * PT;
    float sum = 0.0f;
    #pragma unroll
    for (int t = tid; t < PT; t += 256) sum += e[t];
    #pragma unroll
    for (int o = 16; o > 0; o >>= 1) sum += __shfl_xor_sync(0xFFFFFFFFu, sum, o);
    if (lane == 0) red[wid] = sum;
    __syncthreads();
    const float rcp = 1.0f / (((red[0] + red[1]) + (red[2] + red[3]))
                            + ((red[4] + red[5]) + (red[6] + red[7])));

    // ---- weights for this 128-t chunk ----
    if (tid < TCH) wgt[tid] = e[cb * TCH + tid] * rcp;
    __syncthreads();

    // ---- weighted sum over this chunk ----
    const float4* x = (const float4*)(enc + ((long)b * PT + cb * TCH) * PD);
    float4 a = make_float4(0.f, 0.f, 0.f, 0.f);
    #pragma unroll
    for (int t = tg; t < TCH; t += 8) {
        const float w = wgt[t];
        const float4 v = x[t * 32 + d4];
        a.x = fmaf(w, v.x, a.x); a.y = fmaf(w, v.y, a.y);
        a.z = fmaf(w, v.z, a.z); a.w = fmaf(w, v.w, a.w);
    }
    part[tid] = a;
    __syncthreads();
    if (tg == 0) {
        float4 r = make_float4(0.f, 0.f, 0.f, 0.f);
        #pragma unroll
        for (int j = 0; j < 8; j++) {
            float4 p = part[j * 32 + d4];
            r.x += p.x; r.y += p.y; r.z += p.z; r.w += p.w;
        }
        ((float4*)(g_partial + (b * CH + cb) * PD))[d4] = r;
    }

    // ---- last-block-done final reduce for this batch ----
    __threadfence();
    __syncthreads();
    if (tid == 0) {
        unsigned int v = atomicAdd(&g_cnt[b], 1u);
        isLast = (v == CH - 1);
    }
    __syncthreads();
    if (isLast) {
        if (tid < PD) {
            float accf = 0.0f;
            #pragma unroll
            for (int cc = 0; cc < CH; cc++)
                accf += g_partial[(b * CH + cc) * PD + tid];
            out[b * PD + tid] = accf;
        }
        if (tid == 0) g_cnt[b] = 0;     // reset for next graph replay
    }
}

// ================= launch =================
extern "C" void kernel_launch(void* const* d_in, const int* in_sizes, int n_in,
                              void* d_out, int out_size) {
    const float* enc = (const float*)d_in[0];
    const float* W1w = (const float*)d_in[1];
    const float* W1b = (const float*)d_in[2];
    const float* W2w = (const float*)d_in[3];
    const float* W2b = (const float*)d_in[4];
    const float* Vw  = (const float*)d_in[5];
    float* out = (float*)d_out;

    score_kernel<<<SGRID, K1_THREADS>>>(enc, W1w, W1b, W2w, W2b, Vw);
    dim3 g3(CH, PB);
    context_kernel<<<g3, 256>>>(enc, out);
}